// round 6
// baseline (speedup 1.0000x reference)
#include <cuda_runtime.h>
#include <math.h>

#define N_NODES 50000
#define N_EDGES 1250000
#define D 64
#define L 3

#define CNT_PAD 53248  // 52 * 1024, >= N_NODES, multiple of 4

// Scratch (allocation-free).
__device__ float g_hA[N_NODES * D];
__device__ float g_hB[N_NODES * D];
__device__ int   g_cnt[CNT_PAD];
__device__ int   g_off[N_NODES + 1];
__device__ int   g_cursor[N_NODES];
__device__ int2  g_csr[N_EDGES];     // .x = src node, .y = weight bits

// ---------------------------------------------------------------------------
// Copy input h into out[:, 0:64]; zero the (padded) CSR counters.
__global__ void copy_h_zero_cnt_kernel(const float* __restrict__ h,
                                       float* __restrict__ out) {
    int i = blockIdx.x * blockDim.x + threadIdx.x;
    if (i < CNT_PAD) g_cnt[i] = 0;
    if (i >= N_NODES * 16) return;
    int node = i >> 4;
    int c = i & 15;
    float4 v = ((const float4*)h)[i];
    ((float4*)(out + (size_t)node * 256))[c] = v;
}

// ---------------------------------------------------------------------------
// CSR build pass 1: count in-degree per dst node. 2 edges/thread for ILP.
__global__ void count_kernel(const int* __restrict__ dst) {
    int i = blockIdx.x * blockDim.x + threadIdx.x;
    if (i >= N_EDGES / 2) return;
    int2 d2 = ((const int2*)dst)[i];
    atomicAdd(&g_cnt[d2.x], 1);
    atomicAdd(&g_cnt[d2.y], 1);
}

// ---------------------------------------------------------------------------
// CSR build pass 2: exclusive prefix scan (single block, 1024 thr, int4 loads).
__global__ void scan_kernel() {
    __shared__ int partial[1024];
    const int CHUNK = 52;                 // multiple of 4; 52*1024 = CNT_PAD
    int t = threadIdx.x;
    int start = t * CHUNK;

    int sum = 0;
    #pragma unroll
    for (int i = 0; i < CHUNK / 4; i++) {
        int4 v = ((const int4*)g_cnt)[start / 4 + i];
        sum += v.x + v.y + v.z + v.w;     // padding is zero
    }
    partial[t] = sum;
    __syncthreads();

    for (int off = 1; off < 1024; off <<= 1) {
        int v = (t >= off) ? partial[t - off] : 0;
        __syncthreads();
        partial[t] += v;
        __syncthreads();
    }

    int run = (t == 0) ? 0 : partial[t - 1];
    #pragma unroll 4
    for (int i = 0; i < CHUNK; i++) {
        int idx = start + i;
        if (idx < N_NODES) {
            g_off[idx] = run;
            g_cursor[idx] = run;
            run += g_cnt[idx];
        }
    }
    if (t == 0) g_off[N_NODES] = partial[1023];
}

// ---------------------------------------------------------------------------
// CSR build pass 3: scatter edges into dst-sorted order. 2 edges/thread.
__global__ void fill_kernel(const int* __restrict__ src,
                            const int* __restrict__ dst,
                            const float* __restrict__ ew) {
    int i = blockIdx.x * blockDim.x + threadIdx.x;
    if (i >= N_EDGES / 2) return;
    int2   d2 = ((const int2*)dst)[i];
    int2   s2 = ((const int2*)src)[i];
    float2 w2 = ((const float2*)ew)[i];
    int p0 = atomicAdd(&g_cursor[d2.x], 1);
    int p1 = atomicAdd(&g_cursor[d2.y], 1);
    g_csr[p0] = make_int2(s2.x, __float_as_int(w2.x));
    g_csr[p1] = make_int2(s2.y, __float_as_int(w2.y));
}

// ---------------------------------------------------------------------------
// Fused layer: gather (atomic-free pull over CSR) into smem A-tile, then
// h_next = A @ W + b (+tanh), written to hdst and the output slab.
// Block = 64 nodes, 256 threads. Gather: 4 threads/node, 16 cols each
// (4 independent LDG.128 per edge -> MLP=4). GEMM: 4x4 register tiles.
__global__ void fused_layer_kernel(const float* __restrict__ hsrc,
                                   float* __restrict__ hdst,
                                   const float* __restrict__ W,
                                   const float* __restrict__ b,
                                   float* __restrict__ out,
                                   int out_col_off,
                                   int do_tanh) {
    __shared__ __align__(16) float AsT[64][68];   // [k][row]
    __shared__ __align__(16) float Wsm[64 * 64];  // [k][col]
    __shared__ float bsh[64];

    int t = threadIdx.x;  // 256 threads
    int rowBase = blockIdx.x * 64;

    // Stage W + bias (overlaps with gather loads below).
    #pragma unroll
    for (int i = t; i < 64 * 64; i += 256) Wsm[i] = W[i];
    if (t < 64) bsh[t] = b[t];

    // ---- Gather phase: 4 threads per node ----
    int row  = t >> 2;          // 0..63
    int q    = t & 3;           // quad lane: owns cols q*16 .. q*16+15
    int node = rowBase + row;

    float4 acc0 = make_float4(0.f, 0.f, 0.f, 0.f);
    float4 acc1 = acc0, acc2 = acc0, acc3 = acc0;

    if (node < N_NODES) {
        int beg = g_off[node];
        int end = g_off[node + 1];
        const float4* __restrict__ hrow0 = (const float4*)hsrc + q * 4;
        for (int j = beg; j < end; j++) {
            int2 e = g_csr[j];                     // broadcast within quad
            float w = __int_as_float(e.y);
            const float4* hr = hrow0 + e.x * 16;
            float4 v0 = hr[0];
            float4 v1 = hr[1];
            float4 v2 = hr[2];
            float4 v3 = hr[3];
            acc0.x += v0.x * w; acc0.y += v0.y * w; acc0.z += v0.z * w; acc0.w += v0.w * w;
            acc1.x += v1.x * w; acc1.y += v1.y * w; acc1.z += v1.z * w; acc1.w += v1.w * w;
            acc2.x += v2.x * w; acc2.y += v2.y * w; acc2.z += v2.z * w; acc2.w += v2.w * w;
            acc3.x += v3.x * w; acc3.y += v3.y * w; acc3.z += v3.z * w; acc3.w += v3.w * w;
        }
    }

    // Write transposed into AsT: AsT[k][row] for k in [q*16, q*16+16).
    {
        int kb = q * 16;
        AsT[kb + 0][row]  = acc0.x; AsT[kb + 1][row]  = acc0.y;
        AsT[kb + 2][row]  = acc0.z; AsT[kb + 3][row]  = acc0.w;
        AsT[kb + 4][row]  = acc1.x; AsT[kb + 5][row]  = acc1.y;
        AsT[kb + 6][row]  = acc1.z; AsT[kb + 7][row]  = acc1.w;
        AsT[kb + 8][row]  = acc2.x; AsT[kb + 9][row]  = acc2.y;
        AsT[kb + 10][row] = acc2.z; AsT[kb + 11][row] = acc2.w;
        AsT[kb + 12][row] = acc3.x; AsT[kb + 13][row] = acc3.y;
        AsT[kb + 14][row] = acc3.z; AsT[kb + 15][row] = acc3.w;
    }
    __syncthreads();

    // ---- GEMM phase: 4x4 register tile per thread ----
    int tx = t & 15;   // cols tx*4 .. tx*4+3
    int ty = t >> 4;   // rows ty*4 .. ty*4+3

    float acc[4][4];
    #pragma unroll
    for (int i = 0; i < 4; i++)
        #pragma unroll
        for (int j = 0; j < 4; j++)
            acc[i][j] = bsh[tx * 4 + j];

    #pragma unroll 16
    for (int k = 0; k < 64; k++) {
        float4 a = *(const float4*)&AsT[k][ty * 4];
        float4 w = *(const float4*)&Wsm[k * 64 + tx * 4];
        acc[0][0] += a.x * w.x; acc[0][1] += a.x * w.y; acc[0][2] += a.x * w.z; acc[0][3] += a.x * w.w;
        acc[1][0] += a.y * w.x; acc[1][1] += a.y * w.y; acc[1][2] += a.y * w.z; acc[1][3] += a.y * w.w;
        acc[2][0] += a.z * w.x; acc[2][1] += a.z * w.y; acc[2][2] += a.z * w.z; acc[2][3] += a.z * w.w;
        acc[3][0] += a.w * w.x; acc[3][1] += a.w * w.y; acc[3][2] += a.w * w.z; acc[3][3] += a.w * w.w;
    }

    #pragma unroll
    for (int i = 0; i < 4; i++) {
        int grow = rowBase + ty * 4 + i;
        if (grow >= N_NODES) continue;
        float4 r = make_float4(acc[i][0], acc[i][1], acc[i][2], acc[i][3]);
        if (do_tanh) {
            r.x = tanhf(r.x); r.y = tanhf(r.y); r.z = tanhf(r.z); r.w = tanhf(r.w);
        }
        *(float4*)(hdst + (size_t)grow * 64 + tx * 4) = r;
        *(float4*)(out + (size_t)grow * 256 + out_col_off + tx * 4) = r;
    }
}

// ---------------------------------------------------------------------------
extern "C" void kernel_launch(void* const* d_in, const int* in_sizes, int n_in,
                              void* d_out, int out_size) {
    const float* h   = (const float*)d_in[0];  // [N, 64]
    const float* ew  = (const float*)d_in[1];  // [E]
    const float* Ws  = (const float*)d_in[2];  // [3, 64, 64]
    const float* bs  = (const float*)d_in[3];  // [3, 64]
    const int*   src = (const int*)d_in[4];    // [E]
    const int*   dst = (const int*)d_in[5];    // [E]
    float*       out = (float*)d_out;          // [N, 256]

    // out[:, 0:64] = h; zero degree counters.
    copy_h_zero_cnt_kernel<<<(N_NODES * 16 + 255) / 256, 256>>>(h, out);

    // Build CSR (by dst) once — graph is constant across layers.
    count_kernel<<<(N_EDGES / 2 + 255) / 256, 256>>>(dst);
    scan_kernel<<<1, 1024>>>();
    fill_kernel<<<(N_EDGES / 2 + 255) / 256, 256>>>(src, dst, ew);

    // Ping-pong hidden-state buffers (fused kernel reads prev, writes next).
    float* hA = nullptr; float* hB = nullptr;
    cudaGetSymbolAddress((void**)&hA, g_hA);
    cudaGetSymbolAddress((void**)&hB, g_hB);

    const float* hread = h;
    float* hwrite = hA;
    for (int l = 0; l < L; l++) {
        fused_layer_kernel<<<(N_NODES + 63) / 64, 256>>>(
            hread, hwrite, Ws + l * 64 * 64, bs + l * 64,
            out, (l + 1) * 64, (l < L - 1) ? 1 : 0);
        hread = hwrite;
        hwrite = (hwrite == hA) ? hB : hA;
    }
}